// round 2
// baseline (speedup 1.0000x reference)
#include <cuda_runtime.h>
#include <cuda_fp16.h>
#include <cstdint>

// ---------------- problem dims ----------------
#define M_TOTAL 16384
#define N_TOTAL 12288
#define K_TOTAL 4096

// ---------------- tile config ----------------
#define BM 128
#define BN 128
#define BK 64
#define STAGES 3
#define NKT (K_TOTAL / BK)        // 64 k-tiles
#define THREADS 256

// fp16 scratch (static device arrays: allocation-free)
__device__ __half g_A[(size_t)M_TOTAL * K_TOTAL];   // 134 MB
__device__ __half g_B[(size_t)N_TOTAL * K_TOTAL];   // 100 MB

// SMEM: per stage: A 128 rows x 128B + B 128 rows x 128B
#define B_OFF        (BM * 128)                 // 16384
#define STAGE_BYTES  (BM * 128 + BN * 128)      // 32768
#define SMEM_TOTAL   (STAGES * STAGE_BYTES)     // 98304

#define SWZ(o) ((o) ^ (((o) >> 3) & 0x70))

// ---------------- PTX helpers ----------------
__device__ __forceinline__ uint32_t smem_u32(const void* p) {
    uint32_t a;
    asm("{ .reg .u64 t; cvta.to.shared.u64 t, %1; cvt.u32.u64 %0, t; }" : "=r"(a) : "l"(p));
    return a;
}
__device__ __forceinline__ void cp16(uint32_t s, const void* g) {
    asm volatile("cp.async.cg.shared.global [%0], [%1], 16;" :: "r"(s), "l"(g) : "memory");
}
#define CP_COMMIT() asm volatile("cp.async.commit_group;" ::: "memory")
#define CP_WAIT2()  asm volatile("cp.async.wait_group 2;" ::: "memory")

__device__ __forceinline__ void ldsm4(uint32_t* r, uint32_t addr) {
    asm volatile("ldmatrix.sync.aligned.m8n8.x4.shared.b16 {%0,%1,%2,%3}, [%4];"
                 : "=r"(r[0]), "=r"(r[1]), "=r"(r[2]), "=r"(r[3]) : "r"(addr));
}
__device__ __forceinline__ void mma16816(float* c, const uint32_t* a, const uint32_t* b) {
    asm volatile(
        "mma.sync.aligned.m16n8k16.row.col.f32.f16.f16.f32 "
        "{%0,%1,%2,%3}, {%4,%5,%6,%7}, {%8,%9}, {%0,%1,%2,%3};"
        : "+f"(c[0]), "+f"(c[1]), "+f"(c[2]), "+f"(c[3])
        : "r"(a[0]), "r"(a[1]), "r"(a[2]), "r"(a[3]), "r"(b[0]), "r"(b[1]));
}

// ---------------- fp32 -> fp16 conversion ----------------
__global__ void cvt_kernel(const float* __restrict__ src, __half* __restrict__ dst, int n8) {
    int i = blockIdx.x * blockDim.x + threadIdx.x;
    if (i >= n8) return;
    const float4* s = reinterpret_cast<const float4*>(src) + 2 * (size_t)i;
    float4 a = s[0], b = s[1];
    __half2 h0 = __floats2half2_rn(a.x, a.y);
    __half2 h1 = __floats2half2_rn(a.z, a.w);
    __half2 h2 = __floats2half2_rn(b.x, b.y);
    __half2 h3 = __floats2half2_rn(b.z, b.w);
    uint4 o;
    o.x = *reinterpret_cast<unsigned*>(&h0);
    o.y = *reinterpret_cast<unsigned*>(&h1);
    o.z = *reinterpret_cast<unsigned*>(&h2);
    o.w = *reinterpret_cast<unsigned*>(&h3);
    reinterpret_cast<uint4*>(dst)[i] = o;
}

// ---------------- main GEMM kernel (mma.sync / HMMA) ----------------
extern "C" __global__ void __launch_bounds__(THREADS, 2)
qkv_gemm_kernel(float* __restrict__ out) {
    extern __shared__ char smem[];
    uint32_t sb = smem_u32(smem);
    int tid = threadIdx.x;
    int wid = tid >> 5;
    int l   = tid & 31;

    // mt fastest: consecutive CTAs share the same B tile (L2 reuse)
    int mt = blockIdx.x & 127;          // M/BM = 128
    int nt = blockIdx.x >> 7;           // 96 n-tiles
    int m0 = mt * BM;
    int n0 = nt * BN;

    int wm = wid & 1;                   // warp m index (2)
    int wn = wid >> 1;                  // warp n index (4) -> warp tile 64x32

    // ----- cp.async loader setup: each thread loads 4x16B of A and 4x16B of B per stage -----
    int lrow = tid >> 1;                // 0..127
    int lhalf = tid & 1;                // which 64B half of the 128B row
    const __half* aRow = g_A + (size_t)(m0 + lrow) * K_TOTAL + lhalf * 32;
    const __half* bRow = g_B + (size_t)(n0 + lrow) * K_TOTAL + lhalf * 32;
    uint32_t swz[4];
    #pragma unroll
    for (int c = 0; c < 4; c++)
        swz[c] = SWZ((uint32_t)(lrow * 128 + (lhalf * 4 + c) * 16));

    // ----- ldmatrix per-lane base offsets (unswizzled; swizzle applied per kk) -----
    // A: m16k16 tiles; lanes 0-15 -> rows 0-15 col 0, lanes 16-31 -> rows 0-15 col 8
    uint32_t aoff[4];
    #pragma unroll
    for (int mi = 0; mi < 4; mi++)
        aoff[mi] = (uint32_t)((wm * 64 + mi * 16 + (l & 15)) * 128 + (l >> 4) * 16);
    // B: x4 covers n16 x k16: lanes 0-7 n0-7/k0, 8-15 n0-7/k8, 16-23 n8-15/k0, 24-31 n8-15/k8
    uint32_t boff[2];
    #pragma unroll
    for (int p = 0; p < 2; p++)
        boff[p] = (uint32_t)((wn * 32 + p * 16 + (l & 7) + ((l & 16) >> 1)) * 128
                             + ((l >> 3) & 1) * 16);

    // ----- prologue: fill STAGES pipeline -----
    #pragma unroll
    for (int s = 0; s < STAGES; s++) {
        uint32_t base = sb + s * STAGE_BYTES;
        const __half* ag = aRow + s * BK;
        const __half* bg = bRow + s * BK;
        #pragma unroll
        for (int c = 0; c < 4; c++) {
            cp16(base + swz[c], ag + c * 8);
            cp16(base + B_OFF + swz[c], bg + c * 8);
        }
        CP_COMMIT();
    }

    float acc[4][4][4];
    #pragma unroll
    for (int mi = 0; mi < 4; mi++)
        #pragma unroll
        for (int ni = 0; ni < 4; ni++)
            #pragma unroll
            for (int j = 0; j < 4; j++)
                acc[mi][ni][j] = 0.0f;

    int sidx = 0;
    #pragma unroll 1
    for (int kt = 0; kt < NKT; kt++) {
        CP_WAIT2();                 // stage kt's loads complete (<=2 groups pending)
        __syncthreads();

        uint32_t sbase = sb + sidx * STAGE_BYTES;
        #pragma unroll
        for (int kk = 0; kk < 4; kk++) {
            uint32_t a[4][4], b[2][4];
            #pragma unroll
            for (int mi = 0; mi < 4; mi++)
                ldsm4(a[mi], sbase + SWZ(aoff[mi] + kk * 32));
            #pragma unroll
            for (int p = 0; p < 2; p++)
                ldsm4(b[p], sbase + B_OFF + SWZ(boff[p] + kk * 32));
            #pragma unroll
            for (int mi = 0; mi < 4; mi++)
                #pragma unroll
                for (int ni = 0; ni < 4; ni++)
                    mma16816(acc[mi][ni], a[mi], &b[ni >> 1][(ni & 1) * 2]);
        }
        __syncthreads();            // everyone done reading this stage

        int nkt = kt + STAGES;
        if (nkt < NKT) {
            uint32_t base = sbase;  // reuse the freed buffer
            const __half* ag = aRow + nkt * BK;
            const __half* bg = bRow + nkt * BK;
            #pragma unroll
            for (int c = 0; c < 4; c++) {
                cp16(base + swz[c], ag + c * 8);
                cp16(base + B_OFF + swz[c], bg + c * 8);
            }
        }
        CP_COMMIT();                // commit (possibly empty) to keep group count in step
        sidx = (sidx + 1 == STAGES) ? 0 : sidx + 1;
    }

    // ---------------- epilogue: registers -> gmem with q/k/v segment split ----------------
    int seg = n0 >> 12;                       // which of q/k/v (BN never straddles 4096)
    int colbase = (n0 & 4095) + wn * 32 + (l & 3) * 2;
    int row0 = m0 + wm * 64 + (l >> 2);
    float* ob = out + (size_t)seg * ((size_t)M_TOTAL * 4096);

    #pragma unroll
    for (int mi = 0; mi < 4; mi++) {
        #pragma unroll
        for (int ni = 0; ni < 4; ni++) {
            int r = row0 + mi * 16;
            int c = colbase + ni * 8;
            float2 v0 = make_float2(acc[mi][ni][0], acc[mi][ni][1]);
            float2 v1 = make_float2(acc[mi][ni][2], acc[mi][ni][3]);
            *reinterpret_cast<float2*>(ob + (size_t)r * 4096 + c) = v0;
            *reinterpret_cast<float2*>(ob + (size_t)(r + 8) * 4096 + c) = v1;
        }
    }
}

// ---------------- launch ----------------
extern "C" void kernel_launch(void* const* d_in, const int* in_sizes, int n_in,
                              void* d_out, int out_size) {
    const float* hs = (const float*)d_in[0];   // hidden_states [4,4096,4096]
    const float* w  = (const float*)d_in[1];   // qkv_proj [12288,4096]
    float* out = (float*)d_out;                // q||k||v, 3 x [16384,4096] fp32

    void* pA = nullptr;
    void* pB = nullptr;
    cudaGetSymbolAddress(&pA, g_A);
    cudaGetSymbolAddress(&pB, g_B);

    int nA8 = (M_TOTAL * (K_TOTAL / 8));       // 8388608
    int nB8 = (N_TOTAL * (K_TOTAL / 8));       // 6291456
    cvt_kernel<<<nA8 / 256, 256>>>(hs, (__half*)pA, nA8);
    cvt_kernel<<<nB8 / 256, 256>>>(w,  (__half*)pB, nB8);

    cudaFuncSetAttribute(qkv_gemm_kernel,
                         cudaFuncAttributeMaxDynamicSharedMemorySize, SMEM_TOTAL);
    int grid = (M_TOTAL / BM) * (N_TOTAL / BN);   // 128 * 96 = 12288
    qkv_gemm_kernel<<<grid, THREADS, SMEM_TOTAL>>>(out);
}